// round 4
// baseline (speedup 1.0000x reference)
#include <cuda_runtime.h>

// Problem constants (fixed by the reference):
//   B=4, C=32, H=64, W=64, K=64, pool block 2x2
#define KK     64
#define HW     4096      // H*W
#define MAXN   4096      // worst-case support size cap (actual <= ~950)
#define NBC    128       // B*C
#define NTH    256
#define PER_T  4         // ceil(max_support / NTH); real max support <= ~950 < 1024

// Static device scratch (no allocation allowed). 64*4096*8B = 2 MB.
__device__ int2 g_list[KK * MAXN];  // .x = pixel index, .y = float bits of rf value
__device__ int  g_cnt[KK];

// ---------------------------------------------------------------------------
// Pass 1: deterministic compaction of each RF's nonzero support into a list.
// One CTA per k. Each thread owns a contiguous 16-pixel chunk; chunk counts
// are scanned (Hillis-Steele, fixed order) so list order — and therefore all
// downstream FP summation order — is identical on every call.
// ---------------------------------------------------------------------------
__global__ __launch_bounds__(NTH) void build_lists(const float* __restrict__ rfs) {
    const int k   = blockIdx.x;
    const int tid = threadIdx.x;
    const float* __restrict__ r = rfs + k * HW;

    __shared__ int scan[NTH];

    float vals[16];
    const int base = tid * 16;
#pragma unroll
    for (int i = 0; i < 16; i += 4) {
        float4 v = *reinterpret_cast<const float4*>(r + base + i);
        vals[i] = v.x; vals[i + 1] = v.y; vals[i + 2] = v.z; vals[i + 3] = v.w;
    }
    int c = 0;
#pragma unroll
    for (int i = 0; i < 16; i++) c += (vals[i] > 0.0f);

    scan[tid] = c;
    __syncthreads();
#pragma unroll
    for (int off = 1; off < NTH; off <<= 1) {
        int t = (tid >= off) ? scan[tid - off] : 0;
        __syncthreads();
        scan[tid] += t;
        __syncthreads();
    }

    int pos = scan[tid] - c;  // exclusive prefix
    const int ob = k * MAXN;
#pragma unroll
    for (int i = 0; i < 16; i++) {
        if (vals[i] > 0.0f) {
            g_list[ob + pos] = make_int2(base + i, __float_as_int(vals[i]));
            pos++;
        }
    }
    if (tid == NTH - 1) g_cnt[k] = scan[NTH - 1];
}

// ---------------------------------------------------------------------------
// Pass 2: main fused kernel. One CTA per (b,c). u tile + h accumulator in
// smem. For each k: pass A computes e=exp(u*rf) over the support (registers)
// and block-reduces the denominator; pass B scatters e/denom into h. Pixels
// are unique within one k, and k's are barrier-separated, so scatter is
// race-free without atomics. Epilogue does the 2x2 block max.
//
// Numerics: e/denom == exp(v-m)/(exp(-m)+Sum exp(v-m)) exactly; |v| <~ 6 so
// no stabilizing max is needed in fp32.
// ---------------------------------------------------------------------------
__global__ __launch_bounds__(NTH) void rf_pool_main(const float* __restrict__ u,
                                                    float* __restrict__ out) {
    __shared__ float u_s[HW];
    __shared__ float h_s[HW];
    __shared__ float red[NTH / 32];

    const int bc   = blockIdx.x;
    const int tid  = threadIdx.x;
    const int lane = tid & 31;
    const int wid  = tid >> 5;

    const float* __restrict__ ub = u + bc * HW;
    for (int i = tid; i < HW; i += NTH) {
        u_s[i] = ub[i];
        h_s[i] = 0.0f;
    }
    __syncthreads();

    for (int k = 0; k < KK; k++) {
        const int cnt = g_cnt[k];
        const int2* __restrict__ ls = g_list + k * MAXN;

        // --- pass A: exp + denominator partial sum ---
        float ecache[PER_T];
        int   icache[PER_T];
        float s = 0.0f;
#pragma unroll
        for (int j = 0; j < PER_T; j++) {
            const int t = tid + j * NTH;
            const bool p = (t < cnt);
            int2 ent = p ? ls[t] : make_int2(0, 0);
            float ev = p ? __expf(u_s[ent.x] * __int_as_float(ent.y)) : 0.0f;
            ecache[j] = ev;
            icache[j] = ent.x;
            s += ev;
        }
        // defensive tail (never taken for real inputs: support < PER_T*NTH)
        for (int t = tid + PER_T * NTH; t < cnt; t += NTH) {
            int2 ent = ls[t];
            s += __expf(u_s[ent.x] * __int_as_float(ent.y));
        }

#pragma unroll
        for (int o = 16; o; o >>= 1) s += __shfl_xor_sync(0xffffffffu, s, o);
        if (lane == 0) red[wid] = s;
        __syncthreads();

        float tot = red[0] + red[1] + red[2] + red[3]
                  + red[4] + red[5] + red[6] + red[7];
        const float inv = __fdividef(1.0f, 1.0f + tot);

        // --- pass B: scatter e * inv into h ---
#pragma unroll
        for (int j = 0; j < PER_T; j++) {
            const int t = tid + j * NTH;
            if (t < cnt) h_s[icache[j]] += ecache[j] * inv;
        }
        for (int t = tid + PER_T * NTH; t < cnt; t += NTH) {
            int2 ent = ls[t];
            h_s[ent.x] += __expf(u_s[ent.x] * __int_as_float(ent.y)) * inv;
        }
        __syncthreads();  // protects both red and h_s across k iterations
    }

    // --- epilogue: 2x2 block max pooling, (64,64) -> (32,32) ---
    float* __restrict__ ob = out + bc * 1024;
    for (int o = tid; o < 1024; o += NTH) {
        const int oy = o >> 5;
        const int ox = o & 31;
        const float* r0 = h_s + (oy * 2) * 64 + ox * 2;
        const float* r1 = r0 + 64;
        ob[o] = fmaxf(fmaxf(r0[0], r0[1]), fmaxf(r1[0], r1[1]));
    }
}

extern "C" void kernel_launch(void* const* d_in, const int* in_sizes, int n_in,
                              void* d_out, int out_size) {
    const float* u   = (const float*)d_in[0];  // (B,C,H,W) = 524288 f32
    const float* rfs = (const float*)d_in[1];  // (K,H,W)   = 262144 f32
    float* out = (float*)d_out;                // (B,C,32,32) = 131072 f32

    build_lists<<<KK, NTH>>>(rfs);
    rf_pool_main<<<NBC, NTH>>>(u, out);
}

// round 5
// speedup vs baseline: 1.5122x; 1.5122x over previous
#include <cuda_runtime.h>

// Problem constants (fixed by the reference):
//   B=4, C=32, H=64, W=64, K=64, pool block 2x2
#define KK     64
#define HW     4096      // H*W
#define MAXN   4096      // capacity cap per RF (actual support <= ~950)
#define NBC    128       // B*C
#define NTH    256
#define NWARP  8
#define K_PER_WARP (KK / NWARP)      // 8
#define MAXPL  32        // cached entries per lane (covers cnt <= 1024)

// Static device scratch (no allocation allowed). 64*4096*4B = 1 MB.
// Entry packing: bits[31:20] = pixel index (0..4095), bits[19:0] = rf value
// quantized as round(rf * 1048575). Max abs quantization error 4.8e-7.
__device__ unsigned int g_list[KK * MAXN];
__device__ int          g_cnt[KK];

#define QSCALE   1048575.0f
#define INV_QS   (1.0f / 1048575.0f)

// ---------------------------------------------------------------------------
// Pass 1: deterministic compaction of each RF's nonzero support.
// One CTA per k; chunk counts + fixed-order Hillis-Steele scan give a
// bit-identical list order every call.
// ---------------------------------------------------------------------------
__global__ __launch_bounds__(NTH) void build_lists(const float* __restrict__ rfs) {
    const int k   = blockIdx.x;
    const int tid = threadIdx.x;
    const float* __restrict__ r = rfs + k * HW;

    __shared__ int scan[NTH];

    float vals[16];
    const int base = tid * 16;
#pragma unroll
    for (int i = 0; i < 16; i += 4) {
        float4 v = *reinterpret_cast<const float4*>(r + base + i);
        vals[i] = v.x; vals[i + 1] = v.y; vals[i + 2] = v.z; vals[i + 3] = v.w;
    }
    int c = 0;
#pragma unroll
    for (int i = 0; i < 16; i++) c += (vals[i] > 0.0f);

    scan[tid] = c;
    __syncthreads();
#pragma unroll
    for (int off = 1; off < NTH; off <<= 1) {
        int t = (tid >= off) ? scan[tid - off] : 0;
        __syncthreads();
        scan[tid] += t;
        __syncthreads();
    }

    int pos = scan[tid] - c;  // exclusive prefix
    const int ob = k * MAXN;
#pragma unroll
    for (int i = 0; i < 16; i++) {
        if (vals[i] > 0.0f) {
            unsigned int q = (unsigned int)(vals[i] * QSCALE + 0.5f);
            g_list[ob + pos] = ((unsigned int)(base + i) << 20) | q;
            pos++;
        }
    }
    if (tid == NTH - 1) g_cnt[k] = scan[NTH - 1];
}

// ---------------------------------------------------------------------------
// Pass 2: one CTA per (b,c); one WARP per k (8 k's per warp, sequentially).
// Zero block barriers in the mainloop: each warp reduces its denominator with
// shuffles and scatters into a warp-private h slice in dynamic smem.
// Epilogue sums the 8 partials in fixed order and takes the 2x2 block max.
//
// Numerics: e/denom == exp(v-m)/(exp(-m)+Sum exp(v-m)) exactly; |v| small
// in fp32, no stabilizing max needed.
// ---------------------------------------------------------------------------
__global__ __launch_bounds__(NTH, 1) void rf_pool_main(const float* __restrict__ u,
                                                       float* __restrict__ out) {
    extern __shared__ float smem[];
    float* u_s = smem;           // HW floats
    float* h_s = smem + HW;      // NWARP * HW floats (warp-private partials)

    const int bc   = blockIdx.x;
    const int tid  = threadIdx.x;
    const int lane = tid & 31;
    const int wid  = tid >> 5;
    float* __restrict__ hw = h_s + wid * HW;

    // load u tile, zero all partial accumulators (vectorized)
    const float4* __restrict__ ub4 = reinterpret_cast<const float4*>(u + bc * HW);
    float4* u4 = reinterpret_cast<float4*>(u_s);
    float4* h4 = reinterpret_cast<float4*>(h_s);
    for (int i = tid; i < HW / 4; i += NTH) u4[i] = ub4[i];
    const float4 z4 = make_float4(0.f, 0.f, 0.f, 0.f);
    for (int i = tid; i < NWARP * HW / 4; i += NTH) h4[i] = z4;
    __syncthreads();

    for (int kk = 0; kk < K_PER_WARP; kk++) {
        const int k   = wid * K_PER_WARP + kk;
        const int cnt = g_cnt[k];
        const unsigned int* __restrict__ ls = g_list + k * MAXN;

        // --- pass A: exp + denominator (warp-only reduce) ---
        float e[MAXPL];
        int   id[MAXPL];
        float s = 0.0f;
#pragma unroll
        for (int j = 0; j < MAXPL; j++) {
            const int t = lane + j * 32;
            const bool p = (t < cnt);
            unsigned int ent = p ? ls[t] : 0u;
            const int   idx = (int)(ent >> 20);
            const float rv  = (float)(ent & 0xFFFFFu) * INV_QS;
            float ev = p ? __expf(u_s[idx] * rv) : 0.0f;
            e[j] = ev; id[j] = idx;
            s += ev;
        }
        // defensive tail (not taken for real inputs: support < 1024)
        for (int t = lane + MAXPL * 32; t < cnt; t += 32) {
            unsigned int ent = ls[t];
            s += __expf(u_s[ent >> 20] * (float)(ent & 0xFFFFFu) * INV_QS);
        }

#pragma unroll
        for (int o = 16; o; o >>= 1) s += __shfl_xor_sync(0xffffffffu, s, o);
        const float inv = __fdividef(1.0f, 1.0f + s);

        // --- pass B: scatter into warp-private h (race-free, no atomics) ---
#pragma unroll
        for (int j = 0; j < MAXPL; j++) {
            if (lane + j * 32 < cnt) hw[id[j]] += e[j] * inv;
        }
        for (int t = lane + MAXPL * 32; t < cnt; t += 32) {
            unsigned int ent = ls[t];
            hw[ent >> 20] += __expf(u_s[ent >> 20] * (float)(ent & 0xFFFFFu) * INV_QS) * inv;
        }
    }
    __syncthreads();

    // --- epilogue: fixed-order sum of 8 partials + 2x2 block max ---
    float* __restrict__ ob = out + bc * 1024;
    for (int o = tid; o < 1024; o += NTH) {
        const int oy = o >> 5;
        const int ox = o & 31;
        const int p00 = (oy * 2) * 64 + ox * 2;
        float a = 0.f, b = 0.f, c = 0.f, d = 0.f;
#pragma unroll
        for (int w = 0; w < NWARP; w++) {
            const float* __restrict__ h = h_s + w * HW + p00;
            a += h[0]; b += h[1]; c += h[64]; d += h[65];
        }
        ob[o] = fmaxf(fmaxf(a, b), fmaxf(c, d));
    }
}

extern "C" void kernel_launch(void* const* d_in, const int* in_sizes, int n_in,
                              void* d_out, int out_size) {
    const float* u   = (const float*)d_in[0];  // (B,C,H,W) = 524288 f32
    const float* rfs = (const float*)d_in[1];  // (K,H,W)   = 262144 f32
    float* out = (float*)d_out;                // (B,C,32,32) = 131072 f32

    const int smem_bytes = (HW + NWARP * HW) * (int)sizeof(float);  // 147456
    cudaFuncSetAttribute(rf_pool_main,
                         cudaFuncAttributeMaxDynamicSharedMemorySize, smem_bytes);

    build_lists<<<KK, NTH>>>(rfs);
    rf_pool_main<<<NBC, NTH, smem_bytes>>>(u, out);
}